// round 8
// baseline (speedup 1.0000x reference)
#include <cuda_runtime.h>

#define V 6
#define U 4
#define NSTATE (V*U)   // 24
#define STEPS 63       // 64th step's output is discarded by the reference

__device__ __forceinline__ float mufu_tanh(float x) {
    float t;
    asm("tanh.approx.f32 %0, %1;" : "=f"(t) : "f"(x));
    return t;
}
__device__ __forceinline__ float mufu_sigmoid(float x) {
    float t;
    float hx = 0.5f * x;
    asm("tanh.approx.f32 %0, %1;" : "=f"(t) : "f"(hx));
    return fmaf(0.5f, t, 0.5f);
}

// Fused: every block redundantly computes the 63-step recurrence in warp 0
// (hidden under each warp's own pre-issued global loads), then applies it.
// No cross-block communication; deterministic; single launch.
__global__ void __launch_bounds__(256) fused_kernel(
    const float4* __restrict__ lsx,
    const float4* __restrict__ lsy,
    float4* __restrict__ out,
    int npairs,
    const float* __restrict__ vel,
    const float* __restrict__ Wix, const float* __restrict__ Wih, const float* __restrict__ bi,
    const float* __restrict__ Wfx, const float* __restrict__ Wfh, const float* __restrict__ bf,
    const float* __restrict__ Wox, const float* __restrict__ Woh, const float* __restrict__ bo,
    const float* __restrict__ Wgx, const float* __restrict__ Wgh, const float* __restrict__ bg,
    const float* __restrict__ linear, const float* __restrict__ bl,
    const float* __restrict__ h0, const float* __restrict__ c0)
{
    __shared__ float s_vels[8];

    const int tid = threadIdx.x;
    const int t   = blockIdx.x * blockDim.x + tid;
    const bool have = (t < npairs);

    // ---- phase 1: everyone issues their streaming loads FIRST ----
    float4 a, b, cc, d, e, f;
    if (have) {
        const float4* px = lsx + 3 * (size_t)t;
        const float4* py = lsy + 3 * (size_t)t;
        a = px[0]; b = px[1]; cc = px[2];
        d = py[0]; e = py[1]; f  = py[2];
    }

    // ---- phase 2: warp 0 computes the recurrence while loads are in flight ----
    if (tid < 32) {
        const unsigned FULL = 0xFFFFFFFFu;
        int lane = tid;
        int tt = (lane < NSTATE) ? lane : 0;
        int j = tt >> 2;
        int base = j << 2;

        float wix = Wix[tt], wfx = Wfx[tt], wox = Wox[tt], wgx = Wgx[tt];
        float bii = bi[tt],  bff = bf[tt],  boo = bo[tt],  bgg = bg[tt];
        float wih[4], wfh[4], woh[4], wgh[4], lin4[4];
#pragma unroll
        for (int k = 0; k < 4; ++k) {
            wih[k] = Wih[tt * 4 + k];
            wfh[k] = Wfh[tt * 4 + k];
            woh[k] = Woh[tt * 4 + k];
            wgh[k] = Wgh[tt * 4 + k];
            lin4[k] = linear[j * 4 + k];
        }
        float blj = bl[j];
        float h = h0[tt];
        float c = c0[tt];
        float x = vel[j];
        float vacc = 0.0f;

#pragma unroll 1
        for (int s = 0; s < STEPS; ++s) {
            float ha = __shfl_sync(FULL, h, base + 0);
            float hb = __shfl_sync(FULL, h, base + 1);
            float hc = __shfl_sync(FULL, h, base + 2);
            float hd = __shfl_sync(FULL, h, base + 3);

            if (s > 0) {
                float sl = fmaf(lin4[0], ha, fmaf(lin4[1], hb,
                           fmaf(lin4[2], hc, fmaf(lin4[3], hd, blj))));
                x = mufu_tanh(sl);
                vacc += (s == 1) ? 2.0f * x : x;   // scan double-counts out1
            }

            float pf = fmaf(wfh[0], ha, bff); pf = fmaf(wfh[1], hb, pf);
            pf = fmaf(wfh[2], hc, pf);        pf = fmaf(wfh[3], hd, pf);
            pf = fmaf(wfx, x, pf);
            float ft = mufu_sigmoid(pf);

            float pi = fmaf(wih[0], ha, bii); pi = fmaf(wih[1], hb, pi);
            pi = fmaf(wih[2], hc, pi);        pi = fmaf(wih[3], hd, pi);
            pi = fmaf(wix, x, pi);
            float po = fmaf(woh[0], ha, boo); po = fmaf(woh[1], hb, po);
            po = fmaf(woh[2], hc, po);        po = fmaf(woh[3], hd, po);
            po = fmaf(wox, x, po);
            float pg = fmaf(wgh[0], ha, bgg); pg = fmaf(wgh[1], hb, pg);
            pg = fmaf(wgh[2], hc, pg);        pg = fmaf(wgh[3], hd, pg);
            pg = fmaf(wgx, x, pg);

            float it = mufu_sigmoid(pi);
            float ot = mufu_sigmoid(po);
            float gt = mufu_sigmoid(pg);      // reference: sigmoid here too

            c = fmaf(ft, c, it * gt);
            h = ot * mufu_sigmoid(c);         // reference: sigmoid, not tanh
        }

        // final out_63 from h_63
        {
            float ha = __shfl_sync(FULL, h, base + 0);
            float hb = __shfl_sync(FULL, h, base + 1);
            float hc = __shfl_sync(FULL, h, base + 2);
            float hd = __shfl_sync(FULL, h, base + 3);
            float sl = fmaf(lin4[0], ha, fmaf(lin4[1], hb,
                       fmaf(lin4[2], hc, fmaf(lin4[3], hd, blj))));
            vacc += mufu_tanh(sl);
        }

        if (lane < NSTATE && (tt & 3) == 0) s_vels[j] = vacc;
    }

    __syncthreads();

    // ---- phase 3: apply (loads already in registers) ----
    if (!have) return;

    float v0 = s_vels[0], v1 = s_vels[1], v2 = s_vels[2];
    float v3 = s_vels[3], v4 = s_vels[4], v5 = s_vels[5];

    float fx0 = fmaf(a.x, v0, fmaf(a.y, v1, fmaf(a.z, v2,
                fmaf(a.w, v3, fmaf(b.x, v4, b.y * v5)))));
    float fx1 = fmaf(b.z, v0, fmaf(b.w, v1, fmaf(cc.x, v2,
                fmaf(cc.y, v3, fmaf(cc.z, v4, cc.w * v5)))));
    float fy0 = fmaf(d.x, v0, fmaf(d.y, v1, fmaf(d.z, v2,
                fmaf(d.w, v3, fmaf(e.x, v4, e.y * v5)))));
    float fy1 = fmaf(e.z, v0, fmaf(e.w, v1, fmaf(f.x, v2,
                fmaf(f.y, v3, fmaf(f.z, v4, f.w * v5)))));

    out[t] = make_float4(fx0, fy0, fx1, fy1);
}

extern "C" void kernel_launch(void* const* d_in, const int* in_sizes, int n_in,
                              void* d_out, int out_size)
{
    const float* vel = (const float*)d_in[0];
    const float* Lsx = (const float*)d_in[1];
    const float* Lsy = (const float*)d_in[2];
    const float* Wix = (const float*)d_in[3];
    const float* Wih = (const float*)d_in[4];
    const float* bi  = (const float*)d_in[5];
    const float* Wfx = (const float*)d_in[6];
    const float* Wfh = (const float*)d_in[7];
    const float* bf  = (const float*)d_in[8];
    const float* Wox = (const float*)d_in[9];
    const float* Woh = (const float*)d_in[10];
    const float* bo  = (const float*)d_in[11];
    const float* Wgx = (const float*)d_in[12];
    const float* Wgh = (const float*)d_in[13];
    const float* bg  = (const float*)d_in[14];
    const float* linear = (const float*)d_in[15];
    const float* bl  = (const float*)d_in[16];
    const float* h0  = (const float*)d_in[17];
    const float* c0  = (const float*)d_in[18];

    int N = in_sizes[1] / V;       // pixels
    int npairs = N / 2;

    fused_kernel<<<(npairs + 255) / 256, 256>>>(
        (const float4*)Lsx, (const float4*)Lsy, (float4*)d_out, npairs,
        vel, Wix, Wih, bi, Wfx, Wfh, bf, Wox, Woh, bo, Wgx, Wgh, bg,
        linear, bl, h0, c0);
}

// round 9
// speedup vs baseline: 1.0953x; 1.0953x over previous
#include <cuda_runtime.h>

#define V 6
#define U 4
#define NSTATE (V*U)   // 24
#define STEPS 63       // 64th step's output is discarded by the reference

__device__ float g_vels[8];
__device__ int   g_flag = 0;
__device__ int   g_done = 0;

__device__ __forceinline__ float mufu_tanh(float x) {
    float t;
    asm("tanh.approx.f32 %0, %1;" : "=f"(t) : "f"(x));
    return t;
}
__device__ __forceinline__ float mufu_sigmoid(float x) {
    float t;
    float hx = 0.5f * x;
    asm("tanh.approx.f32 %0, %1;" : "=f"(t) : "f"(hx));
    return fmaf(0.5f, t, 0.5f);
}

// Single kernel: block 0 = recurrence producer; blocks 1.. = R1-shape apply
// consumers gated by a flag they check AFTER issuing their loads.
__global__ void __launch_bounds__(256, 8) fused_kernel(
    const float4* __restrict__ lsx,
    const float4* __restrict__ lsy,
    float4* __restrict__ out,
    int npairs,
    const float* __restrict__ vel,
    const float* __restrict__ Wix, const float* __restrict__ Wih, const float* __restrict__ bi,
    const float* __restrict__ Wfx, const float* __restrict__ Wfh, const float* __restrict__ bf,
    const float* __restrict__ Wox, const float* __restrict__ Woh, const float* __restrict__ bo,
    const float* __restrict__ Wgx, const float* __restrict__ Wgh, const float* __restrict__ bg,
    const float* __restrict__ linear, const float* __restrict__ bl,
    const float* __restrict__ h0, const float* __restrict__ c0)
{
    const int tid = threadIdx.x;

    if (blockIdx.x == 0) {
        // ================= producer: recurrence (R7 math, warp 0) =================
        if (tid < 32) {
            const unsigned FULL = 0xFFFFFFFFu;
            int lane = tid;
            int t = (lane < NSTATE) ? lane : 0;
            int j = t >> 2;
            int base = j << 2;

            float wix = Wix[t], wfx = Wfx[t], wox = Wox[t], wgx = Wgx[t];
            float bii = bi[t],  bff = bf[t],  boo = bo[t],  bgg = bg[t];
            float wih[4], wfh[4], woh[4], wgh[4], lin4[4];
#pragma unroll
            for (int k = 0; k < 4; ++k) {
                wih[k] = Wih[t * 4 + k];
                wfh[k] = Wfh[t * 4 + k];
                woh[k] = Woh[t * 4 + k];
                wgh[k] = Wgh[t * 4 + k];
                lin4[k] = linear[j * 4 + k];
            }
            float blj = bl[j];
            float h = h0[t];
            float c = c0[t];
            float x = vel[j];
            float vacc = 0.0f;

#pragma unroll 1
            for (int s = 0; s < STEPS; ++s) {
                float ha = __shfl_sync(FULL, h, base + 0);
                float hb = __shfl_sync(FULL, h, base + 1);
                float hc = __shfl_sync(FULL, h, base + 2);
                float hd = __shfl_sync(FULL, h, base + 3);

                if (s > 0) {
                    float sl = fmaf(lin4[0], ha, fmaf(lin4[1], hb,
                               fmaf(lin4[2], hc, fmaf(lin4[3], hd, blj))));
                    x = mufu_tanh(sl);
                    vacc += (s == 1) ? 2.0f * x : x;   // scan double-counts out1
                }

                float pf = fmaf(wfh[0], ha, bff); pf = fmaf(wfh[1], hb, pf);
                pf = fmaf(wfh[2], hc, pf);        pf = fmaf(wfh[3], hd, pf);
                pf = fmaf(wfx, x, pf);
                float ft = mufu_sigmoid(pf);

                float pi = fmaf(wih[0], ha, bii); pi = fmaf(wih[1], hb, pi);
                pi = fmaf(wih[2], hc, pi);        pi = fmaf(wih[3], hd, pi);
                pi = fmaf(wix, x, pi);
                float po = fmaf(woh[0], ha, boo); po = fmaf(woh[1], hb, po);
                po = fmaf(woh[2], hc, po);        po = fmaf(woh[3], hd, po);
                po = fmaf(wox, x, po);
                float pg = fmaf(wgh[0], ha, bgg); pg = fmaf(wgh[1], hb, pg);
                pg = fmaf(wgh[2], hc, pg);        pg = fmaf(wgh[3], hd, pg);
                pg = fmaf(wgx, x, pg);

                float it = mufu_sigmoid(pi);
                float ot = mufu_sigmoid(po);
                float gt = mufu_sigmoid(pg);      // reference: sigmoid here too

                c = fmaf(ft, c, it * gt);
                h = ot * mufu_sigmoid(c);         // reference: sigmoid, not tanh
            }

            {
                float ha = __shfl_sync(FULL, h, base + 0);
                float hb = __shfl_sync(FULL, h, base + 1);
                float hc = __shfl_sync(FULL, h, base + 2);
                float hd = __shfl_sync(FULL, h, base + 3);
                float sl = fmaf(lin4[0], ha, fmaf(lin4[1], hb,
                           fmaf(lin4[2], hc, fmaf(lin4[3], hd, blj))));
                vacc += mufu_tanh(sl);
            }

            if (lane < NSTATE && (t & 3) == 0) g_vels[j] = vacc;
            __threadfence();
            if (lane == 0) *((volatile int*)&g_flag) = 1;
        }
    } else {
        // ================= consumers: R1 apply shape, loads BEFORE the wait =====
        int t = (blockIdx.x - 1) * blockDim.x + tid;   // exact: grid-1 blocks cover npairs
        bool have = (t < npairs);

        float4 a, b, cc, d, e, f;
        if (have) {
            const float4* px = lsx + 3 * (size_t)t;
            const float4* py = lsy + 3 * (size_t)t;
            a = px[0]; b = px[1]; cc = px[2];
            d = py[0]; e = py[1]; f  = py[2];
        }

        // one poller per block; loads are already in flight
        if (tid == 0) {
            while (*((volatile int*)&g_flag) == 0) __nanosleep(256);
        }
        __syncthreads();
        __threadfence();   // acquire: order g_vels reads after flag observation

        if (have) {
            float v0 = __ldcg(&g_vels[0]), v1 = __ldcg(&g_vels[1]), v2 = __ldcg(&g_vels[2]);
            float v3 = __ldcg(&g_vels[3]), v4 = __ldcg(&g_vels[4]), v5 = __ldcg(&g_vels[5]);

            float fx0 = fmaf(a.x, v0, fmaf(a.y, v1, fmaf(a.z, v2,
                        fmaf(a.w, v3, fmaf(b.x, v4, b.y * v5)))));
            float fx1 = fmaf(b.z, v0, fmaf(b.w, v1, fmaf(cc.x, v2,
                        fmaf(cc.y, v3, fmaf(cc.z, v4, cc.w * v5)))));
            float fy0 = fmaf(d.x, v0, fmaf(d.y, v1, fmaf(d.z, v2,
                        fmaf(d.w, v3, fmaf(e.x, v4, e.y * v5)))));
            float fy1 = fmaf(e.z, v0, fmaf(e.w, v1, fmaf(f.x, v2,
                        fmaf(f.y, v3, fmaf(f.z, v4, f.w * v5)))));

            out[t] = make_float4(fx0, fy0, fx1, fy1);
        }
    }

    // ======== last-finishing block resets flag+counter (graph-replay safe) ======
    __syncthreads();
    if (tid == 0) {
        int dcount = atomicAdd(&g_done, 1) + 1;
        if (dcount == (int)gridDim.x) {
            atomicExch(&g_done, 0);
            __threadfence();
            atomicExch(&g_flag, 0);
        }
    }
}

extern "C" void kernel_launch(void* const* d_in, const int* in_sizes, int n_in,
                              void* d_out, int out_size)
{
    const float* vel = (const float*)d_in[0];
    const float* Lsx = (const float*)d_in[1];
    const float* Lsy = (const float*)d_in[2];
    const float* Wix = (const float*)d_in[3];
    const float* Wih = (const float*)d_in[4];
    const float* bi  = (const float*)d_in[5];
    const float* Wfx = (const float*)d_in[6];
    const float* Wfh = (const float*)d_in[7];
    const float* bf  = (const float*)d_in[8];
    const float* Wox = (const float*)d_in[9];
    const float* Woh = (const float*)d_in[10];
    const float* bo  = (const float*)d_in[11];
    const float* Wgx = (const float*)d_in[12];
    const float* Wgh = (const float*)d_in[13];
    const float* bg  = (const float*)d_in[14];
    const float* linear = (const float*)d_in[15];
    const float* bl  = (const float*)d_in[16];
    const float* h0  = (const float*)d_in[17];
    const float* c0  = (const float*)d_in[18];

    int N = in_sizes[1] / V;       // pixels
    int npairs = N / 2;
    int nblocks = (npairs + 255) / 256;   // 4050 exactly

    fused_kernel<<<nblocks + 1, 256>>>(
        (const float4*)Lsx, (const float4*)Lsy, (float4*)d_out, npairs,
        vel, Wix, Wih, bi, Wfx, Wfh, bf, Wox, Woh, bo, Wgx, Wgh, bg,
        linear, bl, h0, c0);
}

// round 10
// speedup vs baseline: 1.1452x; 1.0456x over previous
#include <cuda_runtime.h>

#define V 6
#define U 4
#define NSTATE (V*U)   // 24
#define STEPS 63       // 64th step's output is discarded by the reference

__device__ float g_vels[8];
__device__ int   g_flag = 0;
__device__ int   g_done = 0;

__device__ __forceinline__ float mufu_tanh(float x) {
    float t;
    asm("tanh.approx.f32 %0, %1;" : "=f"(t) : "f"(x));
    return t;
}
__device__ __forceinline__ float mufu_sigmoid(float x) {
    float t;
    float hx = 0.5f * x;
    asm("tanh.approx.f32 %0, %1;" : "=f"(t) : "f"(hx));
    return fmaf(0.5f, t, 0.5f);
}

// Block 0 = recurrence producer (weights in SMEM, volatile reads -> low regs).
// Blocks 1.. = R1-shape apply consumers: issue loads, then gate on flag.
__global__ void __launch_bounds__(256) fused_kernel(
    const float4* __restrict__ lsx,
    const float4* __restrict__ lsy,
    float4* __restrict__ out,
    int npairs,
    const float* __restrict__ vel,
    const float* __restrict__ Wix, const float* __restrict__ Wih, const float* __restrict__ bi,
    const float* __restrict__ Wfx, const float* __restrict__ Wfh, const float* __restrict__ bf,
    const float* __restrict__ Wox, const float* __restrict__ Woh, const float* __restrict__ bo,
    const float* __restrict__ Wgx, const float* __restrict__ Wgh, const float* __restrict__ bg,
    const float* __restrict__ linear, const float* __restrict__ bl,
    const float* __restrict__ h0, const float* __restrict__ c0)
{
    // producer weight tables (allocated in every block; 2.5 KB, harmless)
    __shared__ float s_wh[4][NSTATE][4];   // i,f,o,g recurrent rows
    __shared__ float s_wx[4][NSTATE];      // i,f,o,g input weights
    __shared__ float s_b [4][NSTATE];      // biases
    __shared__ float s_lin[NSTATE];
    __shared__ float s_bl[V];

    const int tid = threadIdx.x;

    if (blockIdx.x == 0) {
        // ==================== producer ====================
        if (tid < 32) {
            const unsigned FULL = 0xFFFFFFFFu;
            int lane = tid;
            int t = (lane < NSTATE) ? lane : 0;
            int j = t >> 2;
            int base = j << 2;

            // stage weights into shared (lanes 0..23 fill their own row)
            if (lane < NSTATE) {
#pragma unroll
                for (int k = 0; k < 4; ++k) {
                    s_wh[0][lane][k] = Wih[lane * 4 + k];
                    s_wh[1][lane][k] = Wfh[lane * 4 + k];
                    s_wh[2][lane][k] = Woh[lane * 4 + k];
                    s_wh[3][lane][k] = Wgh[lane * 4 + k];
                }
                s_wx[0][lane] = Wix[lane];
                s_wx[1][lane] = Wfx[lane];
                s_wx[2][lane] = Wox[lane];
                s_wx[3][lane] = Wgx[lane];
                s_b [0][lane] = bi[lane];
                s_b [1][lane] = bf[lane];
                s_b [2][lane] = bo[lane];
                s_b [3][lane] = bg[lane];
                s_lin[lane]   = linear[lane];
                if (lane < V) s_bl[lane] = bl[lane];
            }
            __syncwarp();

            // volatile pointers: keep weight reads as LDS inside the loop
            volatile const float* vwi = &s_wh[0][t][0];
            volatile const float* vwf = &s_wh[1][t][0];
            volatile const float* vwo = &s_wh[2][t][0];
            volatile const float* vwg = &s_wh[3][t][0];
            volatile const float* vlin = &s_lin[base];

            float h = h0[t];
            float c = c0[t];
            float x = vel[j];
            float blj = s_bl[j];
            float vacc = 0.0f;

#pragma unroll 1
            for (int s = 0; s < STEPS; ++s) {
                float ha = __shfl_sync(FULL, h, base + 0);
                float hb = __shfl_sync(FULL, h, base + 1);
                float hc = __shfl_sync(FULL, h, base + 2);
                float hd = __shfl_sync(FULL, h, base + 3);

                if (s > 0) {
                    float sl = fmaf(vlin[0], ha, fmaf(vlin[1], hb,
                               fmaf(vlin[2], hc, fmaf(vlin[3], hd, blj))));
                    x = mufu_tanh(sl);
                    vacc += (s == 1) ? 2.0f * x : x;   // scan double-counts out1
                }

                float pf = fmaf(vwf[0], ha, s_b[1][t]);
                pf = fmaf(vwf[1], hb, pf);
                pf = fmaf(vwf[2], hc, pf);
                pf = fmaf(vwf[3], hd, pf);
                pf = fmaf(s_wx[1][t], x, pf);
                float ft = mufu_sigmoid(pf);

                float pi = fmaf(vwi[0], ha, s_b[0][t]);
                pi = fmaf(vwi[1], hb, pi);
                pi = fmaf(vwi[2], hc, pi);
                pi = fmaf(vwi[3], hd, pi);
                pi = fmaf(s_wx[0][t], x, pi);
                float po = fmaf(vwo[0], ha, s_b[2][t]);
                po = fmaf(vwo[1], hb, po);
                po = fmaf(vwo[2], hc, po);
                po = fmaf(vwo[3], hd, po);
                po = fmaf(s_wx[2][t], x, po);
                float pg = fmaf(vwg[0], ha, s_b[3][t]);
                pg = fmaf(vwg[1], hb, pg);
                pg = fmaf(vwg[2], hc, pg);
                pg = fmaf(vwg[3], hd, pg);
                pg = fmaf(s_wx[3][t], x, pg);

                float it = mufu_sigmoid(pi);
                float ot = mufu_sigmoid(po);
                float gt = mufu_sigmoid(pg);      // reference: sigmoid here too

                c = fmaf(ft, c, it * gt);
                h = ot * mufu_sigmoid(c);         // reference: sigmoid, not tanh
            }

            {
                float ha = __shfl_sync(FULL, h, base + 0);
                float hb = __shfl_sync(FULL, h, base + 1);
                float hc = __shfl_sync(FULL, h, base + 2);
                float hd = __shfl_sync(FULL, h, base + 3);
                float sl = fmaf(vlin[0], ha, fmaf(vlin[1], hb,
                           fmaf(vlin[2], hc, fmaf(vlin[3], hd, blj))));
                vacc += mufu_tanh(sl);
            }

            if (lane < NSTATE && (t & 3) == 0) g_vels[j] = vacc;
            __threadfence();
            if (lane == 0) *((volatile int*)&g_flag) = 1;
        }
    } else {
        // ==================== consumers (R1 apply, loads before wait) ====
        int t = (blockIdx.x - 1) * blockDim.x + tid;
        bool have = (t < npairs);

        float4 a, b, cc, d, e, f;
        if (have) {
            const float4* px = lsx + 3 * (size_t)t;
            const float4* py = lsy + 3 * (size_t)t;
            a = px[0]; b = px[1]; cc = px[2];
            d = py[0]; e = py[1]; f  = py[2];
        }

        if (tid == 0) {
            while (*((volatile int*)&g_flag) == 0) __nanosleep(512);
        }
        __syncthreads();
        __threadfence();   // acquire: order g_vels reads after flag observation

        if (have) {
            float v0 = __ldcg(&g_vels[0]), v1 = __ldcg(&g_vels[1]), v2 = __ldcg(&g_vels[2]);
            float v3 = __ldcg(&g_vels[3]), v4 = __ldcg(&g_vels[4]), v5 = __ldcg(&g_vels[5]);

            float fx0 = fmaf(a.x, v0, fmaf(a.y, v1, fmaf(a.z, v2,
                        fmaf(a.w, v3, fmaf(b.x, v4, b.y * v5)))));
            float fx1 = fmaf(b.z, v0, fmaf(b.w, v1, fmaf(cc.x, v2,
                        fmaf(cc.y, v3, fmaf(cc.z, v4, cc.w * v5)))));
            float fy0 = fmaf(d.x, v0, fmaf(d.y, v1, fmaf(d.z, v2,
                        fmaf(d.w, v3, fmaf(e.x, v4, e.y * v5)))));
            float fy1 = fmaf(e.z, v0, fmaf(e.w, v1, fmaf(f.x, v2,
                        fmaf(f.y, v3, fmaf(f.z, v4, f.w * v5)))));

            out[t] = make_float4(fx0, fy0, fx1, fy1);
        }
    }

    // ===== last-finishing block resets flag+counter (graph-replay safe) =====
    __syncthreads();
    if (tid == 0) {
        int dcount = atomicAdd(&g_done, 1) + 1;
        if (dcount == (int)gridDim.x) {
            atomicExch(&g_done, 0);
            __threadfence();
            atomicExch(&g_flag, 0);
        }
    }
}

extern "C" void kernel_launch(void* const* d_in, const int* in_sizes, int n_in,
                              void* d_out, int out_size)
{
    const float* vel = (const float*)d_in[0];
    const float* Lsx = (const float*)d_in[1];
    const float* Lsy = (const float*)d_in[2];
    const float* Wix = (const float*)d_in[3];
    const float* Wih = (const float*)d_in[4];
    const float* bi  = (const float*)d_in[5];
    const float* Wfx = (const float*)d_in[6];
    const float* Wfh = (const float*)d_in[7];
    const float* bf  = (const float*)d_in[8];
    const float* Wox = (const float*)d_in[9];
    const float* Woh = (const float*)d_in[10];
    const float* bo  = (const float*)d_in[11];
    const float* Wgx = (const float*)d_in[12];
    const float* Wgh = (const float*)d_in[13];
    const float* bg  = (const float*)d_in[14];
    const float* linear = (const float*)d_in[15];
    const float* bl  = (const float*)d_in[16];
    const float* h0  = (const float*)d_in[17];
    const float* c0  = (const float*)d_in[18];

    int N = in_sizes[1] / V;       // pixels
    int npairs = N / 2;
    int nblocks = (npairs + 255) / 256;   // 4050 exactly

    fused_kernel<<<nblocks + 1, 256>>>(
        (const float4*)Lsx, (const float4*)Lsy, (float4*)d_out, npairs,
        vel, Wix, Wih, bi, Wfx, Wfh, bf, Wox, Woh, bo, Wgx, Wgh, bg,
        linear, bl, h0, c0);
}

// round 11
// speedup vs baseline: 2.0883x; 1.8235x over previous
#include <cuda_runtime.h>

#define V 6
#define U 4
#define NSTATE (V*U)   // 24
#define STEPS 63       // 64th step's output is discarded by the reference

#define NFLAG 32
#define FLAG_STRIDE 128   // ints -> 512 B between copies (different L2 slices)

__device__ float g_vels[8];
__device__ int   g_flags[NFLAG * FLAG_STRIDE];
__device__ int   g_done = 0;

__device__ __forceinline__ float mufu_tanh(float x) {
    float t;
    asm("tanh.approx.f32 %0, %1;" : "=f"(t) : "f"(x));
    return t;
}
__device__ __forceinline__ float mufu_sigmoid(float x) {
    float t;
    float hx = 0.5f * x;
    asm("tanh.approx.f32 %0, %1;" : "=f"(t) : "f"(hx));
    return fmaf(0.5f, t, 0.5f);
}

__global__ void __launch_bounds__(256) fused_kernel(
    const float4* __restrict__ lsx,
    const float4* __restrict__ lsy,
    float4* __restrict__ out,
    int npairs,
    const float* __restrict__ vel,
    const float* __restrict__ Wix, const float* __restrict__ Wih, const float* __restrict__ bi,
    const float* __restrict__ Wfx, const float* __restrict__ Wfh, const float* __restrict__ bf,
    const float* __restrict__ Wox, const float* __restrict__ Woh, const float* __restrict__ bo,
    const float* __restrict__ Wgx, const float* __restrict__ Wgh, const float* __restrict__ bg,
    const float* __restrict__ linear, const float* __restrict__ bl,
    const float* __restrict__ h0, const float* __restrict__ c0)
{
    __shared__ float s_wh[4][NSTATE][4];
    __shared__ float s_wx[4][NSTATE];
    __shared__ float s_b [4][NSTATE];
    __shared__ float s_lin[NSTATE];
    __shared__ float s_bl[V];

    const int tid = threadIdx.x;

    if (blockIdx.x == 0) {
        // ==================== producer (warp 0) ====================
        if (tid < 32) {
            const unsigned FULL = 0xFFFFFFFFu;
            int lane = tid;
            int t = (lane < NSTATE) ? lane : 0;
            int j = t >> 2;
            int base = j << 2;

            if (lane < NSTATE) {
#pragma unroll
                for (int k = 0; k < 4; ++k) {
                    s_wh[0][lane][k] = Wih[lane * 4 + k];
                    s_wh[1][lane][k] = Wfh[lane * 4 + k];
                    s_wh[2][lane][k] = Woh[lane * 4 + k];
                    s_wh[3][lane][k] = Wgh[lane * 4 + k];
                }
                s_wx[0][lane] = Wix[lane];
                s_wx[1][lane] = Wfx[lane];
                s_wx[2][lane] = Wox[lane];
                s_wx[3][lane] = Wgx[lane];
                s_b [0][lane] = bi[lane];
                s_b [1][lane] = bf[lane];
                s_b [2][lane] = bo[lane];
                s_b [3][lane] = bg[lane];
                s_lin[lane]   = linear[lane];
                if (lane < V) s_bl[lane] = bl[lane];
            }
            __syncwarp();

            // volatile: keep weights as LDS in-loop -> low register pressure
            volatile const float* vwi = &s_wh[0][t][0];
            volatile const float* vwf = &s_wh[1][t][0];
            volatile const float* vwo = &s_wh[2][t][0];
            volatile const float* vwg = &s_wh[3][t][0];
            volatile const float* vlin = &s_lin[base];

            float h = h0[t];
            float c = c0[t];
            float x = vel[j];
            float blj = s_bl[j];
            float vacc = 0.0f;

#pragma unroll 1
            for (int s = 0; s < STEPS; ++s) {
                float ha = __shfl_sync(FULL, h, base + 0);
                float hb = __shfl_sync(FULL, h, base + 1);
                float hc = __shfl_sync(FULL, h, base + 2);
                float hd = __shfl_sync(FULL, h, base + 3);

                if (s > 0) {
                    float sl = fmaf(vlin[0], ha, fmaf(vlin[1], hb,
                               fmaf(vlin[2], hc, fmaf(vlin[3], hd, blj))));
                    x = mufu_tanh(sl);
                    vacc += (s == 1) ? 2.0f * x : x;   // scan double-counts out1
                }

                float pf = fmaf(vwf[0], ha, s_b[1][t]);
                pf = fmaf(vwf[1], hb, pf);
                pf = fmaf(vwf[2], hc, pf);
                pf = fmaf(vwf[3], hd, pf);
                pf = fmaf(s_wx[1][t], x, pf);
                float ft = mufu_sigmoid(pf);

                float pi = fmaf(vwi[0], ha, s_b[0][t]);
                pi = fmaf(vwi[1], hb, pi);
                pi = fmaf(vwi[2], hc, pi);
                pi = fmaf(vwi[3], hd, pi);
                pi = fmaf(s_wx[0][t], x, pi);
                float po = fmaf(vwo[0], ha, s_b[2][t]);
                po = fmaf(vwo[1], hb, po);
                po = fmaf(vwo[2], hc, po);
                po = fmaf(vwo[3], hd, po);
                po = fmaf(s_wx[2][t], x, po);
                float pg = fmaf(vwg[0], ha, s_b[3][t]);
                pg = fmaf(vwg[1], hb, pg);
                pg = fmaf(vwg[2], hc, pg);
                pg = fmaf(vwg[3], hd, pg);
                pg = fmaf(s_wx[3][t], x, pg);

                float it = mufu_sigmoid(pi);
                float ot = mufu_sigmoid(po);
                float gt = mufu_sigmoid(pg);      // reference: sigmoid here too

                c = fmaf(ft, c, it * gt);
                h = ot * mufu_sigmoid(c);         // reference: sigmoid, not tanh
            }

            {
                float ha = __shfl_sync(FULL, h, base + 0);
                float hb = __shfl_sync(FULL, h, base + 1);
                float hc = __shfl_sync(FULL, h, base + 2);
                float hd = __shfl_sync(FULL, h, base + 3);
                float sl = fmaf(vlin[0], ha, fmaf(vlin[1], hb,
                           fmaf(vlin[2], hc, fmaf(vlin[3], hd, blj))));
                vacc += mufu_tanh(sl);
            }

            if (lane < NSTATE && (t & 3) == 0) g_vels[j] = vacc;
            __threadfence();
            // every lane releases one replicated flag (32 copies, distinct lines)
            *((volatile int*)&g_flags[lane * FLAG_STRIDE]) = 1;
        }
    } else {
        // ==================== consumers (R1 apply shape) ====================
        int t = (blockIdx.x - 1) * blockDim.x + tid;
        bool have = (t < npairs);

        float4 a, b, cc, d, e, f;
        if (have) {
            const float4* px = lsx + 3 * (size_t)t;
            const float4* py = lsy + 3 * (size_t)t;
            a = px[0]; b = px[1]; cc = px[2];
            d = py[0]; e = py[1]; f  = py[2];
        }

        // one poller per block, on this block's replicated flag copy
        if (tid == 0) {
            volatile int* fl = &g_flags[(blockIdx.x & (NFLAG - 1)) * FLAG_STRIDE];
            while (*fl == 0) __nanosleep(512);
        }
        __syncthreads();

        if (have) {
            // PLAIN loads: L1-cacheable. First read per SM is post-write
            // (fence + flag), so the L1 fill is correct; later blocks hit L1.
            float v0 = g_vels[0], v1 = g_vels[1], v2 = g_vels[2];
            float v3 = g_vels[3], v4 = g_vels[4], v5 = g_vels[5];

            float fx0 = fmaf(a.x, v0, fmaf(a.y, v1, fmaf(a.z, v2,
                        fmaf(a.w, v3, fmaf(b.x, v4, b.y * v5)))));
            float fx1 = fmaf(b.z, v0, fmaf(b.w, v1, fmaf(cc.x, v2,
                        fmaf(cc.y, v3, fmaf(cc.z, v4, cc.w * v5)))));
            float fy0 = fmaf(d.x, v0, fmaf(d.y, v1, fmaf(d.z, v2,
                        fmaf(d.w, v3, fmaf(e.x, v4, e.y * v5)))));
            float fy1 = fmaf(e.z, v0, fmaf(e.w, v1, fmaf(f.x, v2,
                        fmaf(f.y, v3, fmaf(f.z, v4, f.w * v5)))));

            out[t] = make_float4(fx0, fy0, fx1, fy1);
        }
    }

    // ===== last-finishing block resets flags+counter (graph-replay safe) =====
    __syncthreads();
    if (tid == 0) {
        int dcount = atomicAdd(&g_done, 1) + 1;
        if (dcount == (int)gridDim.x) {
            for (int k = 0; k < NFLAG; ++k)
                *((volatile int*)&g_flags[k * FLAG_STRIDE]) = 0;
            __threadfence();
            atomicExch(&g_done, 0);
        }
    }
}

extern "C" void kernel_launch(void* const* d_in, const int* in_sizes, int n_in,
                              void* d_out, int out_size)
{
    const float* vel = (const float*)d_in[0];
    const float* Lsx = (const float*)d_in[1];
    const float* Lsy = (const float*)d_in[2];
    const float* Wix = (const float*)d_in[3];
    const float* Wih = (const float*)d_in[4];
    const float* bi  = (const float*)d_in[5];
    const float* Wfx = (const float*)d_in[6];
    const float* Wfh = (const float*)d_in[7];
    const float* bf  = (const float*)d_in[8];
    const float* Wox = (const float*)d_in[9];
    const float* Woh = (const float*)d_in[10];
    const float* bo  = (const float*)d_in[11];
    const float* Wgx = (const float*)d_in[12];
    const float* Wgh = (const float*)d_in[13];
    const float* bg  = (const float*)d_in[14];
    const float* linear = (const float*)d_in[15];
    const float* bl  = (const float*)d_in[16];
    const float* h0  = (const float*)d_in[17];
    const float* c0  = (const float*)d_in[18];

    int N = in_sizes[1] / V;       // pixels
    int npairs = N / 2;
    int nblocks = (npairs + 255) / 256;   // 4050 exactly

    fused_kernel<<<nblocks + 1, 256>>>(
        (const float4*)Lsx, (const float4*)Lsy, (float4*)d_out, npairs,
        vel, Wix, Wih, bi, Wfx, Wfh, bf, Wox, Woh, bo, Wgx, Wgh, bg,
        linear, bl, h0, c0);
}

// round 12
// speedup vs baseline: 2.8470x; 1.3633x over previous
#include <cuda_runtime.h>

#define V 6
#define U 4
#define NSTATE (V*U)   // 24
#define STEPS 63       // 64th step's output is discarded by the reference

__device__ float g_vels[8];

__device__ __forceinline__ float mufu_tanh(float x) {
    float t;
    asm("tanh.approx.f32 %0, %1;" : "=f"(t) : "f"(x));
    return t;
}
__device__ __forceinline__ float mufu_sigmoid(float x) {
    float t;
    float hx = 0.5f * x;
    asm("tanh.approx.f32 %0, %1;" : "=f"(t) : "f"(hx));
    return fmaf(0.5f, t, 0.5f);
}

// R7-proven register-resident recurrence; PDL trigger at entry so the apply
// kernel launches (and pre-issues its loads) while this runs.
__global__ void recurrence_kernel(
    const float* __restrict__ vel,
    const float* __restrict__ Wix, const float* __restrict__ Wih, const float* __restrict__ bi,
    const float* __restrict__ Wfx, const float* __restrict__ Wfh, const float* __restrict__ bf,
    const float* __restrict__ Wox, const float* __restrict__ Woh, const float* __restrict__ bo,
    const float* __restrict__ Wgx, const float* __restrict__ Wgh, const float* __restrict__ bg,
    const float* __restrict__ linear, const float* __restrict__ bl,
    const float* __restrict__ h0, const float* __restrict__ c0)
{
#if defined(__CUDA_ARCH__) && __CUDA_ARCH__ >= 900
    cudaTriggerProgrammaticLaunchCompletion();
#endif
    const unsigned FULL = 0xFFFFFFFFu;
    int lane = threadIdx.x & 31;
    int t = (lane < NSTATE) ? lane : 0;
    int j = t >> 2;
    int base = j << 2;

    float wix = Wix[t], wfx = Wfx[t], wox = Wox[t], wgx = Wgx[t];
    float bii = bi[t],  bff = bf[t],  boo = bo[t],  bgg = bg[t];
    float wih[4], wfh[4], woh[4], wgh[4], lin4[4];
#pragma unroll
    for (int k = 0; k < 4; ++k) {
        wih[k] = Wih[t * 4 + k];
        wfh[k] = Wfh[t * 4 + k];
        woh[k] = Woh[t * 4 + k];
        wgh[k] = Wgh[t * 4 + k];
        lin4[k] = linear[j * 4 + k];
    }
    float blj = bl[j];
    float h = h0[t];
    float c = c0[t];
    float x = vel[j];
    float vacc = 0.0f;

#pragma unroll 1
    for (int s = 0; s < STEPS; ++s) {
        float ha = __shfl_sync(FULL, h, base + 0);
        float hb = __shfl_sync(FULL, h, base + 1);
        float hc = __shfl_sync(FULL, h, base + 2);
        float hd = __shfl_sync(FULL, h, base + 3);

        if (s > 0) {
            float sl = fmaf(lin4[0], ha, fmaf(lin4[1], hb,
                       fmaf(lin4[2], hc, fmaf(lin4[3], hd, blj))));
            x = mufu_tanh(sl);
            vacc += (s == 1) ? 2.0f * x : x;   // scan double-counts out1
        }

        float pf = fmaf(wfh[0], ha, bff); pf = fmaf(wfh[1], hb, pf);
        pf = fmaf(wfh[2], hc, pf);        pf = fmaf(wfh[3], hd, pf);
        pf = fmaf(wfx, x, pf);
        float ft = mufu_sigmoid(pf);

        float pi = fmaf(wih[0], ha, bii); pi = fmaf(wih[1], hb, pi);
        pi = fmaf(wih[2], hc, pi);        pi = fmaf(wih[3], hd, pi);
        pi = fmaf(wix, x, pi);
        float po = fmaf(woh[0], ha, boo); po = fmaf(woh[1], hb, po);
        po = fmaf(woh[2], hc, po);        po = fmaf(woh[3], hd, po);
        po = fmaf(wox, x, po);
        float pg = fmaf(wgh[0], ha, bgg); pg = fmaf(wgh[1], hb, pg);
        pg = fmaf(wgh[2], hc, pg);        pg = fmaf(wgh[3], hd, pg);
        pg = fmaf(wgx, x, pg);

        float it = mufu_sigmoid(pi);
        float ot = mufu_sigmoid(po);
        float gt = mufu_sigmoid(pg);      // reference: sigmoid here too

        c = fmaf(ft, c, it * gt);
        h = ot * mufu_sigmoid(c);         // reference: sigmoid, not tanh
    }

    {
        float ha = __shfl_sync(FULL, h, base + 0);
        float hb = __shfl_sync(FULL, h, base + 1);
        float hc = __shfl_sync(FULL, h, base + 2);
        float hd = __shfl_sync(FULL, h, base + 3);
        float sl = fmaf(lin4[0], ha, fmaf(lin4[1], hb,
                   fmaf(lin4[2], hc, fmaf(lin4[3], hd, blj))));
        vacc += mufu_tanh(sl);
    }

    if (lane < NSTATE && (t & 3) == 0) g_vels[j] = vacc;
}

// Apply with PDL: pre-issue loads, HW-wait for recurrence completion, then
// PLAIN (L1-cacheable) g_vels reads — the one-variable fix vs R5's __ldcg.
__global__ void __launch_bounds__(256) apply_kernel(
    const float4* __restrict__ lsx,
    const float4* __restrict__ lsy,
    float4* __restrict__ out,
    int npairs)
{
    int t = blockIdx.x * blockDim.x + threadIdx.x;
    bool have = (t < npairs);

    float4 a, b, cc, d, e, f;
    if (have) {
        const float4* px = lsx + 3 * (size_t)t;
        const float4* py = lsy + 3 * (size_t)t;
        a = px[0]; b = px[1]; cc = px[2];
        d = py[0]; e = py[1]; f  = py[2];
    }

#if defined(__CUDA_ARCH__) && __CUDA_ARCH__ >= 900
    cudaGridDependencySynchronize();
#endif
    if (!have) return;

    float v0 = g_vels[0], v1 = g_vels[1], v2 = g_vels[2];
    float v3 = g_vels[3], v4 = g_vels[4], v5 = g_vels[5];

    float fx0 = fmaf(a.x, v0, fmaf(a.y, v1, fmaf(a.z, v2,
                fmaf(a.w, v3, fmaf(b.x, v4, b.y * v5)))));
    float fx1 = fmaf(b.z, v0, fmaf(b.w, v1, fmaf(cc.x, v2,
                fmaf(cc.y, v3, fmaf(cc.z, v4, cc.w * v5)))));
    float fy0 = fmaf(d.x, v0, fmaf(d.y, v1, fmaf(d.z, v2,
                fmaf(d.w, v3, fmaf(e.x, v4, e.y * v5)))));
    float fy1 = fmaf(e.z, v0, fmaf(e.w, v1, fmaf(f.x, v2,
                fmaf(f.y, v3, fmaf(f.z, v4, f.w * v5)))));

    out[t] = make_float4(fx0, fy0, fx1, fy1);
}

extern "C" void kernel_launch(void* const* d_in, const int* in_sizes, int n_in,
                              void* d_out, int out_size)
{
    const float* vel = (const float*)d_in[0];
    const float* Lsx = (const float*)d_in[1];
    const float* Lsy = (const float*)d_in[2];
    const float* Wix = (const float*)d_in[3];
    const float* Wih = (const float*)d_in[4];
    const float* bi  = (const float*)d_in[5];
    const float* Wfx = (const float*)d_in[6];
    const float* Wfh = (const float*)d_in[7];
    const float* bf  = (const float*)d_in[8];
    const float* Wox = (const float*)d_in[9];
    const float* Woh = (const float*)d_in[10];
    const float* bo  = (const float*)d_in[11];
    const float* Wgx = (const float*)d_in[12];
    const float* Wgh = (const float*)d_in[13];
    const float* bg  = (const float*)d_in[14];
    const float* linear = (const float*)d_in[15];
    const float* bl  = (const float*)d_in[16];
    const float* h0  = (const float*)d_in[17];
    const float* c0  = (const float*)d_in[18];

    int N = in_sizes[1] / V;       // pixels
    int npairs = N / 2;

    recurrence_kernel<<<1, 32>>>(vel, Wix, Wih, bi, Wfx, Wfh, bf,
                                 Wox, Woh, bo, Wgx, Wgh, bg,
                                 linear, bl, h0, c0);

    cudaLaunchConfig_t cfg = {};
    cfg.gridDim  = dim3((npairs + 255) / 256);
    cfg.blockDim = dim3(256);
    cfg.dynamicSmemBytes = 0;
    cfg.stream = 0;
    cudaLaunchAttribute attr[1];
    attr[0].id = cudaLaunchAttributeProgrammaticStreamSerialization;
    attr[0].val.programmaticStreamSerializationAllowed = 1;
    cfg.attrs = attr;
    cfg.numAttrs = 1;
    cudaLaunchKernelEx(&cfg, apply_kernel,
                       (const float4*)Lsx, (const float4*)Lsy,
                       (float4*)d_out, npairs);
}